// round 10
// baseline (speedup 1.0000x reference)
#include <cuda_runtime.h>
#include <cuda_fp16.h>
#include <cstdint>

// Problem constants (fixed by the dataset)
#define B_   4
#define NQ_  16384
#define C_   256
#define NH_  8
#define NP_  4
#define H_   128
#define W_   128
#define HD_  32
#define M_   (B_ * NQ_)      // 65536 rows
#define HW_  (H_ * W_)       // 16384

// Scratch (__device__ globals: allocation-free rule)
__device__ float  g_qp       [(size_t)M_ * 96];        // [M, 64 off | 32 logits]
__device__ __half g_vproj_h  [(size_t)B_ * HW_ * C_];  // [B, HW, C] fp16
__device__ __half g_sampled_h[(size_t)M_ * C_];        // [M, C] fp16
__device__ __half g_Wqpt_h   [96 * 256];               // packed W_off|W_attn, [N,K] fp16
__device__ float  g_bqp      [96];
__device__ __half g_Wvt_h    [256 * 256];              // W_v^T  [N,K] fp16
__device__ __half g_Wot_h    [256 * 256];              // W_out^T [N,K] fp16

__device__ __forceinline__ uint32_t smem_u32(const void* p) {
    uint32_t a;
    asm("{ .reg .u64 t; cvta.to.shared.u64 t, %1; cvt.u32.u64 %0, t; }" : "=r"(a) : "l"(p));
    return a;
}
__device__ __forceinline__ void cp16(uint32_t dst, const void* src) {
    asm volatile("cp.async.cg.shared.global [%0], [%1], 16;" :: "r"(dst), "l"(src));
}
// pack two fp32 -> f16x2 (lo = first elem, hi = second)
__device__ __forceinline__ uint32_t pack_h2(float lo, float hi) {
    uint32_t r;
    asm("cvt.rn.f16x2.f32 %0, %1, %2;" : "=r"(r) : "f"(hi), "f"(lo));
    return r;
}

// m16n8k16 fp16 MMA, fp32 accumulate
__device__ __forceinline__ void mma_h(float* d, const uint32_t* a, const uint32_t* b) {
    asm volatile(
        "mma.sync.aligned.m16n8k16.row.col.f32.f16.f16.f32 "
        "{%0,%1,%2,%3}, {%4,%5,%6,%7}, {%8,%9}, {%0,%1,%2,%3};"
        : "+f"(d[0]), "+f"(d[1]), "+f"(d[2]), "+f"(d[3])
        : "r"(a[0]), "r"(a[1]), "r"(a[2]), "r"(a[3]), "r"(b[0]), "r"(b[1]));
}

// ---------------------------------------------------------------------------
// Single pack kernel: Wv^T, Wout^T, packed Wqp^T (all [N,K] fp16) + biases.
// ---------------------------------------------------------------------------
__global__ void pack_all(const float* __restrict__ W_v, const float* __restrict__ W_out,
                         const float* __restrict__ W_off, const float* __restrict__ b_off,
                         const float* __restrict__ W_attn, const float* __restrict__ b_attn)
{
    int idx = blockIdx.x * 256 + threadIdx.x;            // [0, 155648)
    if (idx < 65536) {                                   // W_v^T
        int n = idx >> 8, k = idx & 255;
        g_Wvt_h[idx] = __float2half_rn(W_v[k * 256 + n]);
    } else if (idx < 131072) {                           // W_out^T
        int t = idx - 65536;
        int n = t >> 8, k = t & 255;
        g_Wot_h[t] = __float2half_rn(W_out[k * 256 + n]);
    } else if (idx < 155648) {                           // Wqp^T packed
        int t = idx - 131072;                            // [0, 96*256)
        int n = t >> 8, k = t & 255;
        float v = (n < 64) ? W_off[k * 64 + n] : W_attn[k * 32 + (n - 64)];
        g_Wqpt_h[t] = __float2half_rn(v);
        if (t < 96)
            g_bqp[t] = (t < 64) ? b_off[t] : b_attn[t - 64];
    }
}

// ---------------------------------------------------------------------------
// fp16 mma.sync GEMM. Block tile 128 x (32*JTW), 256 threads = 8 warps
// (2M x 4N), warp tile 64 x (8*JTW). B fp16 in smem; A fp32 (cvt at frag
// load) or fp16 (AHALF). Output fp32 or fp16 (CHALF).
// 3-stage cp.async pipeline, two syncs per K=32 chunk (measured-faster order).
// ---------------------------------------------------------------------------
template<int JTW, bool AHALF, bool CHALF>
__global__ __launch_bounds__(256, 2) void h16_gemm(
    const void* __restrict__ Av, const __half* __restrict__ Bt,
    const float* __restrict__ bias, void* __restrict__ Cv, int Ncols)
{
    constexpr int BN = 32 * JTW;
    constexpr int AROWB = AHALF ? 80 : 160;       // bytes per A smem row (pitch 40 elems)
    constexpr int ASTAGE = 128 * AROWB;
    constexpr int BSTAGE = BN * 80;               // pitch 40 halves
    constexpr int BUNITS = BN * 4;                // 16B units per B chunk

    extern __shared__ char smraw[];
    char* Abuf = smraw;
    char* Bbuf = smraw + 3 * ASTAGE;
    const uint32_t AsU = smem_u32(Abuf);
    const uint32_t BsU = smem_u32(Bbuf);

    const int tid  = threadIdx.x;
    const int lane = tid & 31;
    const int wid  = tid >> 5;
    const int wm = (wid & 1) * 64;
    const int wn = (wid >> 1) * (8 * JTW);
    const int bm = blockIdx.y * 128;
    const int bn = blockIdx.x * BN;

    const int qr = lane >> 2;           // 0..7
    const int qc = lane & 3;            // 0..3

    const float*  Af = (const float*)Av  + (size_t)bm * 256;
    const __half* Ah = (const __half*)Av + (size_t)bm * 256;
    const __half* Bbase = Bt + (size_t)bn * 256;

    float acc[4][JTW][4];
    #pragma unroll
    for (int i = 0; i < 4; i++)
        #pragma unroll
        for (int j = 0; j < JTW; j++)
            #pragma unroll
            for (int q = 0; q < 4; q++) acc[i][j][q] = 0.f;

    auto issue_chunk = [&](int c, int buf) {
        const uint32_t ab = AsU + buf * ASTAGE;
        const uint32_t bb = BsU + buf * BSTAGE;
        if (AHALF) {
            #pragma unroll
            for (int o = 0; o < 2; o++) {             // 512 units
                const int u = tid + o * 256;
                const int row = u >> 2, seg = u & 3;
                cp16(ab + row * 80 + seg * 16,
                     Ah + (size_t)row * 256 + c * 32 + seg * 8);
            }
        } else {
            #pragma unroll
            for (int o = 0; o < 4; o++) {             // 1024 units
                const int u = tid + o * 256;
                const int row = u >> 3, seg = u & 7;
                cp16(ab + row * 160 + seg * 16,
                     Af + (size_t)row * 256 + c * 32 + seg * 4);
            }
        }
        #pragma unroll
        for (int o = 0; o < (BUNITS + 255) / 256; o++) {
            const int u = tid + o * 256;
            if (BUNITS % 256 == 0 || u < BUNITS) {
                const int row = u >> 2, seg = u & 3;
                cp16(bb + row * 80 + seg * 16,
                     Bbase + (size_t)row * 256 + c * 32 + seg * 8);
            }
        }
        asm volatile("cp.async.commit_group;");
    };

    issue_chunk(0, 0);
    issue_chunk(1, 1);

    #pragma unroll 1
    for (int c = 0; c < 8; c++) {
        __syncthreads();                      // all warps done reading buf (c+2)%3
        if (c + 2 < 8) issue_chunk(c + 2, (c + 2) % 3);
        if (c < 6)      { asm volatile("cp.async.wait_group 2;"); }
        else if (c == 6){ asm volatile("cp.async.wait_group 1;"); }
        else            { asm volatile("cp.async.wait_group 0;"); }
        __syncthreads();                      // chunk c visible to all warps

        const char*   Ac = Abuf + (c % 3) * ASTAGE;
        const __half* Bc = (const __half*)(Bbuf + (c % 3) * BSTAGE);

        #pragma unroll
        for (int ks = 0; ks < 2; ks++) {              // K=16 per mma
            const int kc = ks * 16;
            uint32_t af[4][4], bf[JTW][2];
            #pragma unroll
            for (int i = 0; i < 4; i++) {
                if (AHALF) {
                    const __half* ap = (const __half*)Ac + (wm + i * 16 + qr) * 40 + kc + 2 * qc;
                    af[i][0] = *(const uint32_t*)(ap);
                    af[i][1] = *(const uint32_t*)(ap + 8 * 40);
                    af[i][2] = *(const uint32_t*)(ap + 8);
                    af[i][3] = *(const uint32_t*)(ap + 8 * 40 + 8);
                } else {
                    const float* ap = (const float*)Ac + (wm + i * 16 + qr) * 40 + kc + 2 * qc;
                    float2 p0 = *(const float2*)(ap);
                    float2 p1 = *(const float2*)(ap + 8 * 40);
                    float2 p2 = *(const float2*)(ap + 8);
                    float2 p3 = *(const float2*)(ap + 8 * 40 + 8);
                    af[i][0] = pack_h2(p0.x, p0.y);
                    af[i][1] = pack_h2(p1.x, p1.y);
                    af[i][2] = pack_h2(p2.x, p2.y);
                    af[i][3] = pack_h2(p3.x, p3.y);
                }
            }
            #pragma unroll
            for (int j = 0; j < JTW; j++) {
                const __half* bp = Bc + (wn + j * 8 + qr) * 40 + kc + 2 * qc;
                bf[j][0] = *(const uint32_t*)(bp);
                bf[j][1] = *(const uint32_t*)(bp + 8);
            }
            #pragma unroll
            for (int i = 0; i < 4; i++)
                #pragma unroll
                for (int j = 0; j < JTW; j++)
                    mma_h(acc[i][j], af[i], bf[j]);
        }
    }

    // Epilogue
    #pragma unroll
    for (int i = 0; i < 4; i++) {
        const int r0 = bm + wm + i * 16 + qr;
        #pragma unroll
        for (int j = 0; j < JTW; j++) {
            const int col = bn + wn + j * 8 + qc * 2;
            const float b0 = __ldg(&bias[col]), b1 = __ldg(&bias[col + 1]);
            const float v00 = acc[i][j][0] + b0, v01 = acc[i][j][1] + b1;
            const float v10 = acc[i][j][2] + b0, v11 = acc[i][j][3] + b1;
            if (CHALF) {
                __half* Ch = (__half*)Cv;
                *(uint32_t*)(Ch + (size_t)r0 * Ncols + col)       = pack_h2(v00, v01);
                *(uint32_t*)(Ch + (size_t)(r0 + 8) * Ncols + col) = pack_h2(v10, v11);
            } else {
                float* Cf = (float*)Cv;
                *(float2*)(Cf + (size_t)r0 * Ncols + col)       = make_float2(v00, v01);
                *(float2*)(Cf + (size_t)(r0 + 8) * Ncols + col) = make_float2(v10, v11);
            }
        }
    }
}

static constexpr int SMEM_VP  = 3 * (128 * 160 + 128 * 80);  // 92160: JTW4, A fp32
static constexpr int SMEM_OUT = 3 * (128 * 80  + 128 * 80);  // 61440: JTW4, A fp16
static constexpr int SMEM_QP  = 3 * (128 * 160 + 96  * 80);  // 84480: JTW3, A fp32

// ---------------------------------------------------------------------------
// Sampler: ONE warp per query. lane = head*4 + slot; slot covers 8 channels.
// vproj fp16: each corner = one 16B load; fp32 accumulation; fp16 output.
// ---------------------------------------------------------------------------
__global__ __launch_bounds__(256) void sample_kernel8(const float* __restrict__ ref)
{
    const int m    = (blockIdx.x * 256 + threadIdx.x) >> 5;   // query
    const int lane = threadIdx.x & 31;
    const int h = lane >> 2;
    const int s = lane & 3;
    const int b = m >> 14;

    const float rx = __ldg(&ref[2 * m + 0]);
    const float ry = __ldg(&ref[2 * m + 1]);

    const float* qp = g_qp + (size_t)m * 96;

    const float4 lg = *(const float4*)(qp + 64 + h * 4);
    const float mx = fmaxf(fmaxf(lg.x, lg.y), fmaxf(lg.z, lg.w));
    const float e0 = __expf(lg.x - mx), e1 = __expf(lg.y - mx);
    const float e2 = __expf(lg.z - mx), e3 = __expf(lg.w - mx);
    const float inv = 1.f / (e0 + e1 + e2 + e3);
    const float w4[4] = {e0 * inv, e1 * inv, e2 * inv, e3 * inv};

    const float4 o01 = *(const float4*)(qp + h * 8);
    const float4 o23 = *(const float4*)(qp + h * 8 + 4);
    const float offx[4] = {o01.x, o01.z, o23.x, o23.z};
    const float offy[4] = {o01.y, o01.w, o23.y, o23.w};

    const __half* vb = g_vproj_h + (size_t)b * HW_ * C_ + h * HD_ + s * 8;

    float a[8] = {0.f, 0.f, 0.f, 0.f, 0.f, 0.f, 0.f, 0.f};

    #pragma unroll
    for (int p = 0; p < 4; p++) {
        const float lx = fminf(fmaxf(rx + offx[p] * (0.1f / W_), 0.f), 1.f);
        const float ly = fminf(fmaxf(ry + offy[p] * (0.1f / H_), 0.f), 1.f);
        const float ixf = lx * (float)W_ - 0.5f;
        const float iyf = ly * (float)H_ - 0.5f;
        const float x0f = floorf(ixf), y0f = floorf(iyf);
        const float wx = ixf - x0f, wy = iyf - y0f;
        const int x0 = (int)x0f, y0 = (int)y0f;    // in [-1,127]

        const float mx0 = (x0 >= 0)      ? 1.f : 0.f;
        const float mx1 = (x0 + 1 < W_)  ? 1.f : 0.f;
        const float my0 = (y0 >= 0)      ? 1.f : 0.f;
        const float my1 = (y0 + 1 < H_)  ? 1.f : 0.f;

        const int x0c = max(x0, 0),     x1c = min(x0 + 1, W_ - 1);
        const int y0c = max(y0, 0),     y1c = min(y0 + 1, H_ - 1);

        const float wp  = w4[p];
        const float c00 = wp * (1.f - wx) * (1.f - wy) * mx0 * my0;
        const float c10 = wp *        wx  * (1.f - wy) * mx1 * my0;
        const float c01 = wp * (1.f - wx) *        wy  * mx0 * my1;
        const float c11 = wp *        wx  *        wy  * mx1 * my1;

        const uint4 r00 = *(const uint4*)(vb + (size_t)(y0c * W_ + x0c) * C_);
        const uint4 r10 = *(const uint4*)(vb + (size_t)(y0c * W_ + x1c) * C_);
        const uint4 r01 = *(const uint4*)(vb + (size_t)(y1c * W_ + x0c) * C_);
        const uint4 r11 = *(const uint4*)(vb + (size_t)(y1c * W_ + x1c) * C_);

        #pragma unroll
        for (int q = 0; q < 4; q++) {
            const float2 f00 = __half22float2(((const __half2*)&r00)[q]);
            const float2 f10 = __half22float2(((const __half2*)&r10)[q]);
            const float2 f01 = __half22float2(((const __half2*)&r01)[q]);
            const float2 f11 = __half22float2(((const __half2*)&r11)[q]);
            a[2*q+0] = fmaf(c00, f00.x, fmaf(c10, f10.x, fmaf(c01, f01.x, fmaf(c11, f11.x, a[2*q+0]))));
            a[2*q+1] = fmaf(c00, f00.y, fmaf(c10, f10.y, fmaf(c01, f01.y, fmaf(c11, f11.y, a[2*q+1]))));
        }
    }

    uint4 o;
    o.x = pack_h2(a[0], a[1]);
    o.y = pack_h2(a[2], a[3]);
    o.z = pack_h2(a[4], a[5]);
    o.w = pack_h2(a[6], a[7]);
    *(uint4*)(g_sampled_h + (size_t)m * C_ + h * HD_ + s * 8) = o;
}

// ---------------------------------------------------------------------------
extern "C" void kernel_launch(void* const* d_in, const int* in_sizes, int n_in,
                              void* d_out, int out_size)
{
    const float* query  = (const float*)d_in[0];
    const float* refp   = (const float*)d_in[1];
    const float* value  = (const float*)d_in[2];
    const float* W_off  = (const float*)d_in[3];
    const float* b_off  = (const float*)d_in[4];
    const float* W_attn = (const float*)d_in[5];
    const float* b_attn = (const float*)d_in[6];
    const float* W_v    = (const float*)d_in[7];
    const float* b_v    = (const float*)d_in[8];
    const float* W_out  = (const float*)d_in[9];
    const float* b_out  = (const float*)d_in[10];
    float* out = (float*)d_out;

    float *p_qp, *p_bqp;
    __half *p_vp, *p_s, *p_Wqpt, *p_Wvt, *p_Wot;
    cudaGetSymbolAddress((void**)&p_qp,   g_qp);
    cudaGetSymbolAddress((void**)&p_vp,   g_vproj_h);
    cudaGetSymbolAddress((void**)&p_s,    g_sampled_h);
    cudaGetSymbolAddress((void**)&p_Wqpt, g_Wqpt_h);
    cudaGetSymbolAddress((void**)&p_bqp,  g_bqp);
    cudaGetSymbolAddress((void**)&p_Wvt,  g_Wvt_h);
    cudaGetSymbolAddress((void**)&p_Wot,  g_Wot_h);

    cudaFuncSetAttribute((const void*)h16_gemm<3, false, false>, cudaFuncAttributeMaxDynamicSharedMemorySize, SMEM_QP);
    cudaFuncSetAttribute((const void*)h16_gemm<4, false, true>,  cudaFuncAttributeMaxDynamicSharedMemorySize, SMEM_VP);
    cudaFuncSetAttribute((const void*)h16_gemm<4, true,  false>, cudaFuncAttributeMaxDynamicSharedMemorySize, SMEM_OUT);

    // 0) pack/transpose/convert all weights in one launch
    pack_all<<<608, 256>>>(W_v, W_out, W_off, b_off, W_attn, b_attn);
    // 1) fused offset+logit projection: [M,256] x [256,96] -> g_qp (pitch 96)
    h16_gemm<3, false, false><<<dim3(1, M_ / 128), 256, SMEM_QP>>>(query, p_Wqpt, p_bqp, p_qp, 96);
    // 2) value projection: [M,256] x [256,256] -> fp16
    h16_gemm<4, false, true><<<dim3(2, M_ / 128), 256, SMEM_VP>>>(value, p_Wvt, b_v, p_vp, 256);
    // 3) softmax + bilinear deformable sampling (fp16 in/out)
    sample_kernel8<<<M_ / 8, 256>>>(refp);
    // 4) output projection (fp16 A) -> d_out
    h16_gemm<4, true, false><<<dim3(2, M_ / 128), 256, SMEM_OUT>>>(p_s, p_Wot, b_out, out, 256);
}

// round 11
// speedup vs baseline: 1.1032x; 1.1032x over previous
#include <cuda_runtime.h>
#include <cuda_fp16.h>
#include <cstdint>

// Problem constants (fixed by the dataset)
#define B_   4
#define NQ_  16384
#define C_   256
#define NH_  8
#define NP_  4
#define H_   128
#define W_   128
#define HD_  32
#define M_   (B_ * NQ_)      // 65536 rows
#define HW_  (H_ * W_)       // 16384

// Scratch (__device__ globals: allocation-free rule)
__device__ float  g_qp       [(size_t)M_ * 96];        // [M, 64 off | 32 logits]
__device__ __half g_vproj_h  [(size_t)B_ * HW_ * C_];  // [B, HW, C] fp16
__device__ __half g_sampled_h[(size_t)M_ * C_];        // [M, C] fp16
__device__ __half g_Wqpt_h   [96 * 256];               // packed W_off|W_attn, [N,K] fp16
__device__ float  g_bqp      [96];
__device__ __half g_Wvt_h    [256 * 256];              // W_v^T  [N,K] fp16
__device__ __half g_Wot_h    [256 * 256];              // W_out^T [N,K] fp16

__device__ __forceinline__ uint32_t smem_u32(const void* p) {
    uint32_t a;
    asm("{ .reg .u64 t; cvta.to.shared.u64 t, %1; cvt.u32.u64 %0, t; }" : "=r"(a) : "l"(p));
    return a;
}
__device__ __forceinline__ void cp16(uint32_t dst, const void* src) {
    asm volatile("cp.async.cg.shared.global [%0], [%1], 16;" :: "r"(dst), "l"(src));
}
// pack two fp32 -> f16x2 (lo = first elem, hi = second)
__device__ __forceinline__ uint32_t pack_h2(float lo, float hi) {
    uint32_t r;
    asm("cvt.rn.f16x2.f32 %0, %1, %2;" : "=r"(r) : "f"(hi), "f"(lo));
    return r;
}

// m16n8k16 fp16 MMA, fp32 accumulate
__device__ __forceinline__ void mma_h(float* d, const uint32_t* a, const uint32_t* b) {
    asm volatile(
        "mma.sync.aligned.m16n8k16.row.col.f32.f16.f16.f32 "
        "{%0,%1,%2,%3}, {%4,%5,%6,%7}, {%8,%9}, {%0,%1,%2,%3};"
        : "+f"(d[0]), "+f"(d[1]), "+f"(d[2]), "+f"(d[3])
        : "r"(a[0]), "r"(a[1]), "r"(a[2]), "r"(a[3]), "r"(b[0]), "r"(b[1]));
}

// ---------------------------------------------------------------------------
// Single pack kernel: Wv^T, Wout^T, packed Wqp^T (all [N,K] fp16) + biases.
// ---------------------------------------------------------------------------
__global__ void pack_all(const float* __restrict__ W_v, const float* __restrict__ W_out,
                         const float* __restrict__ W_off, const float* __restrict__ b_off,
                         const float* __restrict__ W_attn, const float* __restrict__ b_attn)
{
    int idx = blockIdx.x * 256 + threadIdx.x;            // [0, 155648)
    if (idx < 65536) {                                   // W_v^T
        int n = idx >> 8, k = idx & 255;
        g_Wvt_h[idx] = __float2half_rn(W_v[k * 256 + n]);
    } else if (idx < 131072) {                           // W_out^T
        int t = idx - 65536;
        int n = t >> 8, k = t & 255;
        g_Wot_h[t] = __float2half_rn(W_out[k * 256 + n]);
    } else if (idx < 155648) {                           // Wqp^T packed
        int t = idx - 131072;                            // [0, 96*256)
        int n = t >> 8, k = t & 255;
        float v = (n < 64) ? W_off[k * 64 + n] : W_attn[k * 32 + (n - 64)];
        g_Wqpt_h[t] = __float2half_rn(v);
        if (t < 96)
            g_bqp[t] = (t < 64) ? b_off[t] : b_attn[t - 64];
    }
}

// ---------------------------------------------------------------------------
// fp16 mma.sync GEMM (round-8 measured-best config). Block tile 128 x (16*JT),
// 128 threads = 4 warps (2M x 2N), warp tile 64 x (8*JT). B fp16 in smem;
// A fp32 (cvt at frag load) or fp16 (AHALF). Output fp32 or fp16 (CHALF).
// 3-stage cp.async pipeline, two syncs per K=32 chunk.
// ---------------------------------------------------------------------------
template<int JT, bool AHALF, bool CHALF>
__global__ __launch_bounds__(128, 2) void h16_gemm(
    const void* __restrict__ Av, const __half* __restrict__ Bt,
    const float* __restrict__ bias, void* __restrict__ Cv, int Ncols)
{
    constexpr int BN = 16 * JT;
    constexpr int AROWB = AHALF ? 80 : 160;       // bytes per A smem row (pitch 40 elems)
    constexpr int ASTAGE = 128 * AROWB;
    constexpr int BSTAGE = BN * 80;               // pitch 40 halves

    extern __shared__ char smraw[];
    char* Abuf = smraw;
    char* Bbuf = smraw + 3 * ASTAGE;
    const uint32_t AsU = smem_u32(Abuf);
    const uint32_t BsU = smem_u32(Bbuf);

    const int tid  = threadIdx.x;
    const int lane = tid & 31;
    const int wid  = tid >> 5;
    const int wm = (wid & 1) * 64;
    const int wn = (wid >> 1) * (8 * JT);
    const int bm = blockIdx.y * 128;
    const int bn = blockIdx.x * BN;

    const int qr = lane >> 2;           // 0..7
    const int qc = lane & 3;            // 0..3

    const float*  Af = (const float*)Av  + (size_t)bm * 256;
    const __half* Ah = (const __half*)Av + (size_t)bm * 256;
    const __half* Bbase = Bt + (size_t)bn * 256;

    float acc[4][JT][4];
    #pragma unroll
    for (int i = 0; i < 4; i++)
        #pragma unroll
        for (int j = 0; j < JT; j++)
            #pragma unroll
            for (int q = 0; q < 4; q++) acc[i][j][q] = 0.f;

    auto issue_chunk = [&](int c, int buf) {
        const uint32_t ab = AsU + buf * ASTAGE;
        const uint32_t bb = BsU + buf * BSTAGE;
        if (AHALF) {
            #pragma unroll
            for (int o = 0; o < 4; o++) {
                const int u = tid + o * 128;
                const int row = u >> 2, seg = u & 3;
                cp16(ab + row * 80 + seg * 16,
                     Ah + (size_t)row * 256 + c * 32 + seg * 8);
            }
        } else {
            #pragma unroll
            for (int o = 0; o < 8; o++) {
                const int u = tid + o * 128;
                const int row = u >> 3, seg = u & 7;
                cp16(ab + row * 160 + seg * 16,
                     Af + (size_t)row * 256 + c * 32 + seg * 4);
            }
        }
        #pragma unroll
        for (int o = 0; o < BN / 32; o++) {
            const int u = tid + o * 128;
            const int row = u >> 2, seg = u & 3;
            cp16(bb + row * 80 + seg * 16,
                 Bbase + (size_t)row * 256 + c * 32 + seg * 8);
        }
        asm volatile("cp.async.commit_group;");
    };

    issue_chunk(0, 0);
    issue_chunk(1, 1);

    #pragma unroll 1
    for (int c = 0; c < 8; c++) {
        __syncthreads();                      // all warps done reading buf (c+2)%3
        if (c + 2 < 8) issue_chunk(c + 2, (c + 2) % 3);
        if (c < 6)      { asm volatile("cp.async.wait_group 2;"); }
        else if (c == 6){ asm volatile("cp.async.wait_group 1;"); }
        else            { asm volatile("cp.async.wait_group 0;"); }
        __syncthreads();                      // chunk c visible to all warps

        const char*   Ac = Abuf + (c % 3) * ASTAGE;
        const __half* Bc = (const __half*)(Bbuf + (c % 3) * BSTAGE);

        #pragma unroll
        for (int ks = 0; ks < 2; ks++) {              // K=16 per mma
            const int kc = ks * 16;
            uint32_t af[4][4], bf[JT][2];
            #pragma unroll
            for (int i = 0; i < 4; i++) {
                if (AHALF) {
                    const __half* ap = (const __half*)Ac + (wm + i * 16 + qr) * 40 + kc + 2 * qc;
                    af[i][0] = *(const uint32_t*)(ap);
                    af[i][1] = *(const uint32_t*)(ap + 8 * 40);
                    af[i][2] = *(const uint32_t*)(ap + 8);
                    af[i][3] = *(const uint32_t*)(ap + 8 * 40 + 8);
                } else {
                    const float* ap = (const float*)Ac + (wm + i * 16 + qr) * 40 + kc + 2 * qc;
                    float2 p0 = *(const float2*)(ap);
                    float2 p1 = *(const float2*)(ap + 8 * 40);
                    float2 p2 = *(const float2*)(ap + 8);
                    float2 p3 = *(const float2*)(ap + 8 * 40 + 8);
                    af[i][0] = pack_h2(p0.x, p0.y);
                    af[i][1] = pack_h2(p1.x, p1.y);
                    af[i][2] = pack_h2(p2.x, p2.y);
                    af[i][3] = pack_h2(p3.x, p3.y);
                }
            }
            #pragma unroll
            for (int j = 0; j < JT; j++) {
                const __half* bp = Bc + (wn + j * 8 + qr) * 40 + kc + 2 * qc;
                bf[j][0] = *(const uint32_t*)(bp);
                bf[j][1] = *(const uint32_t*)(bp + 8);
            }
            #pragma unroll
            for (int i = 0; i < 4; i++)
                #pragma unroll
                for (int j = 0; j < JT; j++)
                    mma_h(acc[i][j], af[i], bf[j]);
        }
    }

    // Epilogue
    #pragma unroll
    for (int i = 0; i < 4; i++) {
        const int r0 = bm + wm + i * 16 + qr;
        #pragma unroll
        for (int j = 0; j < JT; j++) {
            const int col = bn + wn + j * 8 + qc * 2;
            const float b0 = __ldg(&bias[col]), b1 = __ldg(&bias[col + 1]);
            const float v00 = acc[i][j][0] + b0, v01 = acc[i][j][1] + b1;
            const float v10 = acc[i][j][2] + b0, v11 = acc[i][j][3] + b1;
            if (CHALF) {
                __half* Ch = (__half*)Cv;
                *(uint32_t*)(Ch + (size_t)r0 * Ncols + col)       = pack_h2(v00, v01);
                *(uint32_t*)(Ch + (size_t)(r0 + 8) * Ncols + col) = pack_h2(v10, v11);
            } else {
                float* Cf = (float*)Cv;
                *(float2*)(Cf + (size_t)r0 * Ncols + col)       = make_float2(v00, v01);
                *(float2*)(Cf + (size_t)(r0 + 8) * Ncols + col) = make_float2(v10, v11);
            }
        }
    }
}

static constexpr int SMEM_VP  = 3 * (128 * 160 + 128 * 80);  // 92160: JT8, A fp32
static constexpr int SMEM_OUT = 3 * (128 * 80  + 128 * 80);  // 61440: JT8, A fp16
static constexpr int SMEM_QP  = 3 * (128 * 160 + 96  * 80);  // 84480: JT6, A fp32

// ---------------------------------------------------------------------------
// Sampler: ONE warp per query. lane = head*4 + slot; slot covers 8 channels.
// Boundary masks folded into predicated coefficients; corner combine done in
// half2 (HFMA2) with fp16 coefficients; cross-point accumulation in fp32.
// ---------------------------------------------------------------------------
__global__ __launch_bounds__(256) void sample_kernel8(const float* __restrict__ ref)
{
    const int m    = (blockIdx.x * 256 + threadIdx.x) >> 5;   // query
    const int lane = threadIdx.x & 31;
    const int h = lane >> 2;
    const int s = lane & 3;
    const int b = m >> 14;

    const float rx = __ldg(&ref[2 * m + 0]);
    const float ry = __ldg(&ref[2 * m + 1]);

    const float* qp = g_qp + (size_t)m * 96;

    const float4 lg = *(const float4*)(qp + 64 + h * 4);
    const float mx = fmaxf(fmaxf(lg.x, lg.y), fmaxf(lg.z, lg.w));
    const float e0 = __expf(lg.x - mx), e1 = __expf(lg.y - mx);
    const float e2 = __expf(lg.z - mx), e3 = __expf(lg.w - mx);
    const float inv = 1.f / (e0 + e1 + e2 + e3);
    const float w4[4] = {e0 * inv, e1 * inv, e2 * inv, e3 * inv};

    const float4 o01 = *(const float4*)(qp + h * 8);
    const float4 o23 = *(const float4*)(qp + h * 8 + 4);
    const float offx[4] = {o01.x, o01.z, o23.x, o23.z};
    const float offy[4] = {o01.y, o01.w, o23.y, o23.w};

    const __half* vb = g_vproj_h + (size_t)b * HW_ * C_ + h * HD_ + s * 8;

    float a[8] = {0.f, 0.f, 0.f, 0.f, 0.f, 0.f, 0.f, 0.f};

    #pragma unroll
    for (int p = 0; p < 4; p++) {
        const float lx = fminf(fmaxf(rx + offx[p] * (0.1f / W_), 0.f), 1.f);
        const float ly = fminf(fmaxf(ry + offy[p] * (0.1f / H_), 0.f), 1.f);
        const float ixf = lx * (float)W_ - 0.5f;
        const float iyf = ly * (float)H_ - 0.5f;
        const float x0f = floorf(ixf), y0f = floorf(iyf);
        const float wx = ixf - x0f, wy = iyf - y0f;
        const int x0 = (int)x0f, y0 = (int)y0f;    // in [-1,127]

        // boundary masks folded into coefficients (selp, no float mask muls)
        const float cx0 = (x0 >= 0)      ? 1.f - wx : 0.f;
        const float cx1 = (x0 < W_ - 1)  ? wx       : 0.f;
        const float wp  = w4[p];
        const float cy0 = (y0 >= 0)      ? wp * (1.f - wy) : 0.f;
        const float cy1 = (y0 < H_ - 1)  ? wp * wy         : 0.f;

        const int x0c = max(x0, 0),     x1c = min(x0 + 1, W_ - 1);
        const int y0c = max(y0, 0),     y1c = min(y0 + 1, H_ - 1);

        // fp16 coefficient broadcasts (1 cvt each)
        const __half2 c00 = __float2half2_rn(cx0 * cy0);
        const __half2 c10 = __float2half2_rn(cx1 * cy0);
        const __half2 c01 = __float2half2_rn(cx0 * cy1);
        const __half2 c11 = __float2half2_rn(cx1 * cy1);

        const uint4 r00 = *(const uint4*)(vb + (size_t)(y0c * W_ + x0c) * C_);
        const uint4 r10 = *(const uint4*)(vb + (size_t)(y0c * W_ + x1c) * C_);
        const uint4 r01 = *(const uint4*)(vb + (size_t)(y1c * W_ + x0c) * C_);
        const uint4 r11 = *(const uint4*)(vb + (size_t)(y1c * W_ + x1c) * C_);

        #pragma unroll
        for (int q = 0; q < 4; q++) {
            __half2 sv = __hmul2(c00, ((const __half2*)&r00)[q]);
            sv = __hfma2(c10, ((const __half2*)&r10)[q], sv);
            sv = __hfma2(c01, ((const __half2*)&r01)[q], sv);
            sv = __hfma2(c11, ((const __half2*)&r11)[q], sv);
            const float2 f = __half22float2(sv);
            a[2 * q + 0] += f.x;
            a[2 * q + 1] += f.y;
        }
    }

    uint4 o;
    o.x = pack_h2(a[0], a[1]);
    o.y = pack_h2(a[2], a[3]);
    o.z = pack_h2(a[4], a[5]);
    o.w = pack_h2(a[6], a[7]);
    *(uint4*)(g_sampled_h + (size_t)m * C_ + h * HD_ + s * 8) = o;
}

// ---------------------------------------------------------------------------
extern "C" void kernel_launch(void* const* d_in, const int* in_sizes, int n_in,
                              void* d_out, int out_size)
{
    const float* query  = (const float*)d_in[0];
    const float* refp   = (const float*)d_in[1];
    const float* value  = (const float*)d_in[2];
    const float* W_off  = (const float*)d_in[3];
    const float* b_off  = (const float*)d_in[4];
    const float* W_attn = (const float*)d_in[5];
    const float* b_attn = (const float*)d_in[6];
    const float* W_v    = (const float*)d_in[7];
    const float* b_v    = (const float*)d_in[8];
    const float* W_out  = (const float*)d_in[9];
    const float* b_out  = (const float*)d_in[10];
    float* out = (float*)d_out;

    float *p_qp, *p_bqp;
    __half *p_vp, *p_s, *p_Wqpt, *p_Wvt, *p_Wot;
    cudaGetSymbolAddress((void**)&p_qp,   g_qp);
    cudaGetSymbolAddress((void**)&p_vp,   g_vproj_h);
    cudaGetSymbolAddress((void**)&p_s,    g_sampled_h);
    cudaGetSymbolAddress((void**)&p_Wqpt, g_Wqpt_h);
    cudaGetSymbolAddress((void**)&p_bqp,  g_bqp);
    cudaGetSymbolAddress((void**)&p_Wvt,  g_Wvt_h);
    cudaGetSymbolAddress((void**)&p_Wot,  g_Wot_h);

    cudaFuncSetAttribute((const void*)h16_gemm<6, false, false>, cudaFuncAttributeMaxDynamicSharedMemorySize, SMEM_QP);
    cudaFuncSetAttribute((const void*)h16_gemm<8, false, true>,  cudaFuncAttributeMaxDynamicSharedMemorySize, SMEM_VP);
    cudaFuncSetAttribute((const void*)h16_gemm<8, true,  false>, cudaFuncAttributeMaxDynamicSharedMemorySize, SMEM_OUT);

    // 0) pack/transpose/convert all weights in one launch
    pack_all<<<608, 256>>>(W_v, W_out, W_off, b_off, W_attn, b_attn);
    // 1) fused offset+logit projection: [M,256] x [256,96] -> g_qp (pitch 96)
    h16_gemm<6, false, false><<<dim3(1, M_ / 128), 128, SMEM_QP>>>(query, p_Wqpt, p_bqp, p_qp, 96);
    // 2) value projection: [M,256] x [256,256] -> fp16
    h16_gemm<8, false, true><<<dim3(2, M_ / 128), 128, SMEM_VP>>>(value, p_Wvt, b_v, p_vp, 256);
    // 3) softmax + bilinear deformable sampling (fp16 in/out, half2 interp)
    sample_kernel8<<<M_ / 8, 256>>>(refp);
    // 4) output projection (fp16 A) -> d_out
    h16_gemm<8, true, false><<<dim3(2, M_ / 128), 128, SMEM_OUT>>>(p_s, p_Wot, b_out, out, 256);
}